// round 13
// baseline (speedup 1.0000x reference)
#include <cuda_runtime.h>
#include <cstdint>
#include <cstddef>

#define T_STEPS 10
#define NB 8

// ---------------- scratch (device globals; no allocation) ----------------
__device__ uint32_t g_spk1[T_STEPS*NB*128*160];      // 32ch masks
__device__ uint32_t g_spk2[T_STEPS*NB*64*80*2];      // 64ch masks
__device__ uint32_t g_spk3[T_STEPS*NB*32*40*2];      // 64ch masks
__device__ uint32_t g_spk4[T_STEPS*NB*16*20*4];      // 128ch masks
__device__ float    g_S[10240*NB];                   // spike counts [k][b]
__device__ float    g_spk1f[NB*4096];                // fc1 spikes

__device__ __forceinline__ float lo32(unsigned long long v){ return __uint_as_float((uint32_t)v); }
__device__ __forceinline__ float hi32(unsigned long long v){ return __uint_as_float((uint32_t)(v>>32)); }

// ---------------- layer 1: conv 2->32 @256x320 + LIF + pool ----------------
// thread = (b, hp, wp, g in 0..1 [16ch], pos in 0..3). 1.31M threads.
__global__ void __launch_bounds__(256) k_l1(const float* __restrict__ x,
                                            const float* __restrict__ w1,
                                            const float* __restrict__ b1) {
    int id  = blockIdx.x*256 + threadIdx.x;
    int pos = id & 3, dh = pos >> 1, dw = pos & 1;
    int g   = (id >> 2) & 1;
    int rid = id >> 3;
    int wp  = rid % 160; rid /= 160;
    int hp  = rid % 128;
    int b   = rid / 128;

    float w0[16], w1r[16], bb[16], m[16];
    #pragma unroll
    for (int oo=0; oo<16; oo++) {
        int o = g*16+oo;
        w0[oo] = w1[2*o]; w1r[oo] = w1[2*o+1]; bb[oo] = b1[o];
        m[oo]  = 0.0f;
    }

    const float* xb0 = x + ((size_t)b)*163840 + (2*hp+dh)*320 + (2*wp+dw);
    #pragma unroll 1
    for (int t=0; t<T_STEPS; t++) {
        const float* xb = xb0 + (size_t)t*NB*163840;
        float x0 = xb[0];
        float x1 = xb[81920];
        uint32_t sb = 0;
        #pragma unroll
        for (int oo=0; oo<16; oo++) {
            float cur = fmaf(w1r[oo], x1, w0[oo]*x0) + bb[oo];
            float mo  = m[oo];
            float mn  = fmaf(0.95f, mo, cur) - ((mo>1.0f)?1.0f:0.0f);
            m[oo] = mn;
            sb |= ((mn>1.0f)?1u:0u) << oo;
        }
        sb <<= (g*16);
        sb |= __shfl_xor_sync(0xffffffffu, sb, 1);
        sb |= __shfl_xor_sync(0xffffffffu, sb, 2);
        sb |= __shfl_xor_sync(0xffffffffu, sb, 4);
        if ((id & 7) == 0)
            g_spk1[((size_t)(t*NB+b)*128 + hp)*160 + wp] = sb;
    }
}

// ---- non-volatile multiplier build: bit C of k -> packed {s,s}, s in {0.0,1.0} ----
template<int C>
__device__ __forceinline__ unsigned long long mkmul(uint32_t k) {
    unsigned long long s;
    asm("{\n\t.reg .b32 t;\n\t"
        "bfe.s32 t, %1, %2, 1;\n\t"
        "and.b32 t, t, 0x3f800000;\n\t"
        "mov.b64 %0, {t, t};\n\t}"
        : "=l"(s) : "r"(k), "n"(C));
    return s;
}

// ---- per-input-channel step over 2 timesteps ----
// Weights loaded in C++ (hoistable LDS.128); multipliers non-volatile (reorderable);
// only the 8 FFMA2 stay volatile-ordered -> exact ascending-channel rn-add chain per t.
// acc layout: a[tt*4 + p], pair p holds output channels (2p, 2p+1).
template<int C>
__device__ __forceinline__ void chan2(uint32_t k0, uint32_t k1,
                                      const float* __restrict__ wtw,
                                      unsigned long long (&a)[8]) {
    ulonglong2 wv0 = *(const ulonglong2*)(wtw + C*8);
    ulonglong2 wv1 = *(const ulonglong2*)(wtw + C*8 + 4);
    unsigned long long s0 = mkmul<C>(k0);
    unsigned long long s1 = mkmul<C>(k1);
    asm volatile(
        "fma.rn.f32x2 %0, %8, %12, %0;\n\t"
        "fma.rn.f32x2 %1, %9, %12, %1;\n\t"
        "fma.rn.f32x2 %2, %10, %12, %2;\n\t"
        "fma.rn.f32x2 %3, %11, %12, %3;\n\t"
        "fma.rn.f32x2 %4, %8, %13, %4;\n\t"
        "fma.rn.f32x2 %5, %9, %13, %5;\n\t"
        "fma.rn.f32x2 %6, %10, %13, %6;\n\t"
        "fma.rn.f32x2 %7, %11, %13, %7;"
        : "+l"(a[0]), "+l"(a[1]), "+l"(a[2]), "+l"(a[3]),
          "+l"(a[4]), "+l"(a[5]), "+l"(a[6]), "+l"(a[7])
        : "l"(wv0.x), "l"(wv0.y), "l"(wv1.x), "l"(wv1.y),
          "l"(s0), "l"(s1));
}

template<int C, int N>
struct Chan2Loop {
    static __device__ __forceinline__ void run(uint32_t k0, uint32_t k1,
                                               const float* __restrict__ wtw,
                                               unsigned long long (&a)[8]) {
        chan2<C>(k0, k1, wtw, a);
        Chan2Loop<C+1, N>::run(k0, k1, wtw, a);
    }
};
template<int N>
struct Chan2Loop<N, N> {
    static __device__ __forceinline__ void run(uint32_t, uint32_t,
                                               const float* __restrict__,
                                               unsigned long long (&)[8]) {}
};

// ------------- conv(1x1 over bitmask spikes)+LIF+pool, OG=8, T in 5 chunks of 2 -------------
template<int CIN, int COUT, int HIN, int WIN, int BS, bool COUNT>
__device__ __forceinline__ void conv_body(const uint32_t* __restrict__ in,
                                          uint8_t* __restrict__ outb,
                                          const float* __restrict__ wg,
                                          const float* __restrict__ bg) {
    constexpr int OG  = 8;
    constexpr int WRD = CIN/32;
    constexpr int HP  = HIN/2, WP = WIN/2;
    constexpr int NBY = COUT/8;

    __shared__ __align__(16) float wt[CIN*OG];      // wt[c][o] (transposed)
    const int ob = blockIdx.y * OG;
    for (int idx = threadIdx.x; idx < CIN*OG; idx += BS) {
        int c = idx / OG, o = idx % OG;
        wt[c*OG + o] = wg[(size_t)(ob+o)*CIN + c];
    }
    __syncthreads();

    int id  = blockIdx.x*BS + threadIdx.x;
    int pos = id & 3, dh = pos >> 1, dw = pos & 1;
    int rid = id >> 2;
    int wp  = rid % WP; rid /= WP;
    int hp  = rid % HP;
    int b   = rid / HP;

    float bb[OG], m[OG], cnt[OG];
    #pragma unroll
    for (int c=0; c<OG; c++) { bb[c] = bg[ob+c]; m[c] = 0.0f; cnt[c] = 0.0f; }

    const uint32_t* ibase = in + (((size_t)b*HIN + 2*hp+dh)*WIN + (2*wp+dw))*WRD;
    const size_t tstride  = (size_t)NB*HIN*WIN*WRD;

    #pragma unroll 1
    for (int chnk=0; chnk<5; chnk++) {
        // stage 2 timesteps of input masks
        uint32_t mk[2][WRD];
        #pragma unroll
        for (int tt=0; tt<2; tt++) {
            const uint32_t* ip = ibase + (size_t)(chnk*2+tt)*tstride;
            if constexpr (WRD == 1) {
                mk[tt][0] = ip[0];
            } else if constexpr (WRD == 2) {
                uint2 v = *(const uint2*)ip; mk[tt][0]=v.x; mk[tt][1]=v.y;
            } else {
                uint4 v = *(const uint4*)ip;
                mk[tt][0]=v.x; mk[tt][1]=v.y; mk[tt][2]=v.z; mk[tt][3]=v.w;
            }
        }

        unsigned long long a[8];
        #pragma unroll
        for (int i=0; i<8; i++) a[i] = 0ULL;

        #pragma unroll
        for (int w=0; w<WRD; w++) {
            Chan2Loop<0, 32>::run(mk[0][w], mk[1][w], wt + w*(32*OG), a);
        }

        // LIF for the 2 timesteps, sequentially
        #pragma unroll
        for (int tt=0; tt<2; tt++) {
            int t = chnk*2 + tt;
            uint32_t sb = 0;
            #pragma unroll
            for (int c=0; c<OG; c++) {
                float curc = (c & 1) ? hi32(a[tt*4 + (c>>1)]) : lo32(a[tt*4 + (c>>1)]);
                float cf = curc + bb[c];
                float mo = m[c];
                float mn = fmaf(0.95f, mo, cf) - ((mo>1.0f)?1.0f:0.0f);
                m[c] = mn;
                sb |= ((mn>1.0f)?1u:0u) << c;
            }
            sb |= __shfl_xor_sync(0xffffffffu, sb, 1);
            sb |= __shfl_xor_sync(0xffffffffu, sb, 2);

            if constexpr (COUNT) {
                #pragma unroll
                for (int c=0; c<OG; c++) cnt[c] += (float)((sb>>c)&1u);
            } else {
                if (pos == 0)
                    outb[(((size_t)(t*NB+b)*HP + hp)*WP + wp)*NBY + blockIdx.y] = (uint8_t)sb;
            }
        }
    }

    if constexpr (COUNT) {
        if (pos == 0) {
            #pragma unroll
            for (int c=0; c<OG; c++)
                g_S[((size_t)(ob+c)*(HP*WP) + hp*WP + wp)*NB + b] = cnt[c];
        }
    }
}

__global__ void __launch_bounds__(128) k_l2(const float* __restrict__ wg, const float* __restrict__ bg){
    conv_body<32,64,128,160,128,false>(g_spk1, (uint8_t*)g_spk2, wg, bg);
}
__global__ void __launch_bounds__(128) k_l3(const float* __restrict__ wg, const float* __restrict__ bg){
    conv_body<64,64,64,80,128,false>(g_spk2, (uint8_t*)g_spk3, wg, bg);
}
__global__ void __launch_bounds__(128) k_l4(const float* __restrict__ wg, const float* __restrict__ bg){
    conv_body<64,128,32,40,128,false>(g_spk3, (uint8_t*)g_spk4, wg, bg);
}
__global__ void __launch_bounds__(128) k_l5(const float* __restrict__ wg, const float* __restrict__ bg){
    conv_body<128,128,16,20,128,true>(g_spk4, nullptr, wg, bg);
}

// ------------- fc1: [8,10240] @ [4096,10240]^T, spike -------------
__global__ void __launch_bounds__(128) k_fc1(const float* __restrict__ w,
                                             const float* __restrict__ bias) {
    __shared__ __align__(16) float sw[16*260];
    __shared__ __align__(16) float ss[8*260];
    int tid = threadIdx.x;
    int jl  = tid >> 3, b = tid & 7;
    int j   = blockIdx.x*16 + jl;

    float a0=0.f, a1=0.f, a2=0.f, a3=0.f;

    #pragma unroll 1
    for (int kt=0; kt<40; kt++) {
        __syncthreads();
        for (int i = tid; i < 1024; i += 128) {
            int r = i >> 6, c4 = i & 63;
            float4 v = *(const float4*)&w[(size_t)(blockIdx.x*16 + r)*10240 + kt*256 + c4*4];
            *(float4*)&sw[r*260 + c4*4] = v;
        }
        for (int i = tid; i < 2048; i += 128) {
            int k = i >> 3, bi = i & 7;
            ss[bi*260 + k] = g_S[(size_t)(kt*256 + k)*8 + bi];
        }
        __syncthreads();

        #pragma unroll 4
        for (int kk=0; kk<256; kk+=4) {
            float4 wv = *(const float4*)&sw[jl*260 + kk];
            float4 sv = *(const float4*)&ss[b*260 + kk];
            a0 = fmaf(wv.x, sv.x, a0);
            a1 = fmaf(wv.y, sv.y, a1);
            a2 = fmaf(wv.z, sv.z, a2);
            a3 = fmaf(wv.w, sv.w, a3);
        }
    }
    float mem = ((a0+a1)+(a2+a3)) + bias[j];
    g_spk1f[b*4096 + j] = (mem>1.0f) ? 1.0f : 0.0f;
}

// ------------- fc2: [8,4096] @ [4,4096]^T -> out[8,4] -------------
__global__ void __launch_bounds__(1024) k_fc2(const float* __restrict__ w,
                                              const float* __restrict__ bias,
                                              float* __restrict__ out) {
    int wid  = threadIdx.x >> 5;
    int lane = threadIdx.x & 31;
    int b = wid >> 2, i = wid & 3;
    float acc = 0.0f;
    for (int j = lane*4; j < 4096; j += 128) {
        float4 s  = *(const float4*)&g_spk1f[b*4096 + j];
        float4 wv = *(const float4*)&w[(size_t)i*4096 + j];
        acc = fmaf(wv.x, s.x, acc);
        acc = fmaf(wv.y, s.y, acc);
        acc = fmaf(wv.z, s.z, acc);
        acc = fmaf(wv.w, s.w, acc);
    }
    #pragma unroll
    for (int off=16; off; off>>=1) acc += __shfl_xor_sync(0xffffffffu, acc, off);
    if (lane == 0) out[b*4 + i] = acc + bias[i];
}

extern "C" void kernel_launch(void* const* d_in, const int* in_sizes, int n_in,
                              void* d_out, int out_size) {
    const float* x     = (const float*)d_in[0];
    const float* w1    = (const float*)d_in[1];
    const float* b1    = (const float*)d_in[2];
    const float* w2    = (const float*)d_in[3];
    const float* b2    = (const float*)d_in[4];
    const float* w3    = (const float*)d_in[5];
    const float* b3    = (const float*)d_in[6];
    const float* w4    = (const float*)d_in[7];
    const float* b4    = (const float*)d_in[8];
    const float* w5    = (const float*)d_in[9];
    const float* b5    = (const float*)d_in[10];
    const float* fc1_w = (const float*)d_in[11];
    const float* fc1_b = (const float*)d_in[12];
    const float* fc2_w = (const float*)d_in[13];
    const float* fc2_b = (const float*)d_in[14];

    k_l1<<<5120, 256>>>(x, w1, b1);                   // 1.31M threads, 16ch each
    { dim3 g(1280, 8); k_l2<<<g, 128>>>(w2, b2); }
    { dim3 g(320, 8);  k_l3<<<g, 128>>>(w3, b3); }
    { dim3 g(80, 16);  k_l4<<<g, 128>>>(w4, b4); }
    { dim3 g(20, 16);  k_l5<<<g, 128>>>(w5, b5); }
    k_fc1<<<256, 128>>>(fc1_w, fc1_b);
    k_fc2<<<1, 1024>>>(fc2_w, fc2_b, (float*)d_out);
}

// round 14
// speedup vs baseline: 1.1153x; 1.1153x over previous
#include <cuda_runtime.h>
#include <cstdint>
#include <cstddef>

#define T_STEPS 10
#define NB 8

// ---------------- scratch (device globals; no allocation) ----------------
__device__ uint32_t g_spk1[T_STEPS*NB*128*160];      // 32ch masks
__device__ uint32_t g_spk2[T_STEPS*NB*64*80*2];      // 64ch masks
__device__ uint32_t g_spk3[T_STEPS*NB*32*40*2];      // 64ch masks
__device__ uint32_t g_spk4[T_STEPS*NB*16*20*4];      // 128ch masks
__device__ float    g_S[10240*NB];                   // spike counts [k][b]
__device__ float    g_spk1f[NB*4096];                // fc1 spikes

__device__ __forceinline__ float lo32(unsigned long long v){ return __uint_as_float((uint32_t)v); }
__device__ __forceinline__ float hi32(unsigned long long v){ return __uint_as_float((uint32_t)(v>>32)); }

// ---------------- layer 1: conv 2->32 @256x320 + LIF + pool ----------------
__global__ void __launch_bounds__(256) k_l1(const float* __restrict__ x,
                                            const float* __restrict__ w1,
                                            const float* __restrict__ b1) {
    int id  = blockIdx.x*256 + threadIdx.x;
    int pos = id & 3, dh = pos >> 1, dw = pos & 1;
    int g   = (id >> 2) & 1;
    int rid = id >> 3;
    int wp  = rid % 160; rid /= 160;
    int hp  = rid % 128;
    int b   = rid / 128;

    float w0[16], w1r[16], bb[16], m[16];
    #pragma unroll
    for (int oo=0; oo<16; oo++) {
        int o = g*16+oo;
        w0[oo] = w1[2*o]; w1r[oo] = w1[2*o+1]; bb[oo] = b1[o];
        m[oo]  = 0.0f;
    }

    const float* xb0 = x + ((size_t)b)*163840 + (2*hp+dh)*320 + (2*wp+dw);
    #pragma unroll 1
    for (int t=0; t<T_STEPS; t++) {
        const float* xb = xb0 + (size_t)t*NB*163840;
        float x0 = xb[0];
        float x1 = xb[81920];
        uint32_t sb = 0;
        #pragma unroll
        for (int oo=0; oo<16; oo++) {
            float cur = fmaf(w1r[oo], x1, w0[oo]*x0) + bb[oo];
            float mo  = m[oo];
            float mn  = fmaf(0.95f, mo, cur) - ((mo>1.0f)?1.0f:0.0f);
            m[oo] = mn;
            sb |= ((mn>1.0f)?1u:0u) << oo;
        }
        sb <<= (g*16);
        sb |= __shfl_xor_sync(0xffffffffu, sb, 1);
        sb |= __shfl_xor_sync(0xffffffffu, sb, 2);
        sb |= __shfl_xor_sync(0xffffffffu, sb, 4);
        if ((id & 7) == 0)
            g_spk1[((size_t)(t*NB+b)*128 + hp)*160 + wp] = sb;
    }
}

// ---- OG=16, 2 timesteps per step: 4 LDS.128 + 6 ALU amortized over 16 FFMA2 ----
// Bit-exact per (t, output ch): one rn-add per set bit, ascending channel order.
// acc layout: a[tt*8 + p], pair p holds output channels (2p, 2p+1).
template<int C>
__device__ __forceinline__ void chan2x16(uint32_t k0, uint32_t k1,
                                         uint32_t sbw, unsigned long long (&a)[16]) {
    asm volatile("{\n\t"
        ".reg .b32 b0,b1;\n\t"
        ".reg .b64 s0,s1,w0,w1,w2,w3,w4,w5,w6,w7;\n\t"
        "bfe.s32 b0, %16, %18, 1;\n\t"
        "bfe.s32 b1, %17, %18, 1;\n\t"
        "and.b32 b0, b0, 0x3f800000;\n\t"
        "and.b32 b1, b1, 0x3f800000;\n\t"
        "mov.b64 s0, {b0, b0};\n\t"
        "mov.b64 s1, {b1, b1};\n\t"
        "ld.shared.v2.u64 {w0,w1}, [%19+%20];\n\t"
        "ld.shared.v2.u64 {w2,w3}, [%19+%21];\n\t"
        "ld.shared.v2.u64 {w4,w5}, [%19+%22];\n\t"
        "ld.shared.v2.u64 {w6,w7}, [%19+%23];\n\t"
        "fma.rn.f32x2 %0, w0, s0, %0;\n\t"
        "fma.rn.f32x2 %1, w1, s0, %1;\n\t"
        "fma.rn.f32x2 %2, w2, s0, %2;\n\t"
        "fma.rn.f32x2 %3, w3, s0, %3;\n\t"
        "fma.rn.f32x2 %4, w4, s0, %4;\n\t"
        "fma.rn.f32x2 %5, w5, s0, %5;\n\t"
        "fma.rn.f32x2 %6, w6, s0, %6;\n\t"
        "fma.rn.f32x2 %7, w7, s0, %7;\n\t"
        "fma.rn.f32x2 %8, w0, s1, %8;\n\t"
        "fma.rn.f32x2 %9, w1, s1, %9;\n\t"
        "fma.rn.f32x2 %10, w2, s1, %10;\n\t"
        "fma.rn.f32x2 %11, w3, s1, %11;\n\t"
        "fma.rn.f32x2 %12, w4, s1, %12;\n\t"
        "fma.rn.f32x2 %13, w5, s1, %13;\n\t"
        "fma.rn.f32x2 %14, w6, s1, %14;\n\t"
        "fma.rn.f32x2 %15, w7, s1, %15;\n\t}"
        : "+l"(a[0]),  "+l"(a[1]),  "+l"(a[2]),  "+l"(a[3]),
          "+l"(a[4]),  "+l"(a[5]),  "+l"(a[6]),  "+l"(a[7]),
          "+l"(a[8]),  "+l"(a[9]),  "+l"(a[10]), "+l"(a[11]),
          "+l"(a[12]), "+l"(a[13]), "+l"(a[14]), "+l"(a[15])
        : "r"(k0), "r"(k1), "n"(C), "r"(sbw),
          "n"(C*64), "n"(C*64+16), "n"(C*64+32), "n"(C*64+48));
}

template<int C, int N>
struct Chan2x16Loop {
    static __device__ __forceinline__ void run(uint32_t k0, uint32_t k1,
                                               uint32_t sbw, unsigned long long (&a)[16]) {
        chan2x16<C>(k0, k1, sbw, a);
        Chan2x16Loop<C+1, N>::run(k0, k1, sbw, a);
    }
};
template<int N>
struct Chan2x16Loop<N, N> {
    static __device__ __forceinline__ void run(uint32_t, uint32_t,
                                               uint32_t, unsigned long long (&)[16]) {}
};

// ---- OG=8 variant (for l5/COUNT), 2 timesteps: R12's proven block ----
template<int C>
__device__ __forceinline__ void chan2x8(uint32_t k0, uint32_t k1,
                                        uint32_t sbw, unsigned long long (&a)[8]) {
    asm volatile("{\n\t"
        ".reg .b32 b0,b1;\n\t"
        ".reg .b64 s0,s1,w0,w1,w2,w3;\n\t"
        "bfe.s32 b0, %8, %10, 1;\n\t"
        "bfe.s32 b1, %9, %10, 1;\n\t"
        "and.b32 b0, b0, 0x3f800000;\n\t"
        "and.b32 b1, b1, 0x3f800000;\n\t"
        "mov.b64 s0, {b0, b0};\n\t"
        "mov.b64 s1, {b1, b1};\n\t"
        "ld.shared.v2.u64 {w0,w1}, [%11+%12];\n\t"
        "ld.shared.v2.u64 {w2,w3}, [%11+%13];\n\t"
        "fma.rn.f32x2 %0, w0, s0, %0;\n\t"
        "fma.rn.f32x2 %1, w1, s0, %1;\n\t"
        "fma.rn.f32x2 %2, w2, s0, %2;\n\t"
        "fma.rn.f32x2 %3, w3, s0, %3;\n\t"
        "fma.rn.f32x2 %4, w0, s1, %4;\n\t"
        "fma.rn.f32x2 %5, w1, s1, %5;\n\t"
        "fma.rn.f32x2 %6, w2, s1, %6;\n\t"
        "fma.rn.f32x2 %7, w3, s1, %7;\n\t}"
        : "+l"(a[0]), "+l"(a[1]), "+l"(a[2]), "+l"(a[3]),
          "+l"(a[4]), "+l"(a[5]), "+l"(a[6]), "+l"(a[7])
        : "r"(k0), "r"(k1),
          "n"(C), "r"(sbw), "n"(C*32), "n"(C*32+16));
}

template<int C, int N>
struct Chan2x8Loop {
    static __device__ __forceinline__ void run(uint32_t k0, uint32_t k1,
                                               uint32_t sbw, unsigned long long (&a)[8]) {
        chan2x8<C>(k0, k1, sbw, a);
        Chan2x8Loop<C+1, N>::run(k0, k1, sbw, a);
    }
};
template<int N>
struct Chan2x8Loop<N, N> {
    static __device__ __forceinline__ void run(uint32_t, uint32_t,
                                               uint32_t, unsigned long long (&)[8]) {}
};

// ------------- conv(1x1 over bitmask spikes)+LIF+pool, T in 5 chunks of 2 -------------
// Spill-safe shape: #pragma unroll 1 chunk loop, loop-local arrays only.
template<int CIN, int COUT, int OG, int HIN, int WIN, int BS, bool COUNT>
__device__ __forceinline__ void conv_body(const uint32_t* __restrict__ in,
                                          uint8_t* __restrict__ outb,
                                          const float* __restrict__ wg,
                                          const float* __restrict__ bg) {
    constexpr int WRD = CIN/32;
    constexpr int HP  = HIN/2, WP = WIN/2;
    constexpr int NBY = COUT/8;
    constexpr int NPT = OG/2;   // acc pairs per timestep

    __shared__ __align__(16) float wt[CIN*OG];      // wt[c][o] (transposed)
    const int ob = blockIdx.y * OG;
    for (int idx = threadIdx.x; idx < CIN*OG; idx += BS) {
        int c = idx / OG, o = idx % OG;
        wt[c*OG + o] = wg[(size_t)(ob+o)*CIN + c];
    }
    __syncthreads();

    uint32_t sbase;
    asm("{ .reg .u64 t0; cvta.to.shared.u64 t0, %1; cvt.u32.u64 %0, t0; }"
        : "=r"(sbase) : "l"(wt));

    int id  = blockIdx.x*BS + threadIdx.x;
    int pos = id & 3, dh = pos >> 1, dw = pos & 1;
    int rid = id >> 2;
    int wp  = rid % WP; rid /= WP;
    int hp  = rid % HP;
    int b   = rid / HP;

    float bb[OG], m[OG], cnt[OG];
    #pragma unroll
    for (int c=0; c<OG; c++) { bb[c] = bg[ob+c]; m[c] = 0.0f; cnt[c] = 0.0f; }

    const uint32_t* ibase = in + (((size_t)b*HIN + 2*hp+dh)*WIN + (2*wp+dw))*WRD;
    const size_t tstride  = (size_t)NB*HIN*WIN*WRD;

    #pragma unroll 1
    for (int chnk=0; chnk<5; chnk++) {
        // stage 2 timesteps of input masks
        uint32_t mk[2][WRD];
        #pragma unroll
        for (int tt=0; tt<2; tt++) {
            const uint32_t* ip = ibase + (size_t)(chnk*2+tt)*tstride;
            if constexpr (WRD == 1) {
                mk[tt][0] = ip[0];
            } else if constexpr (WRD == 2) {
                uint2 v = *(const uint2*)ip; mk[tt][0]=v.x; mk[tt][1]=v.y;
            } else {
                uint4 v = *(const uint4*)ip;
                mk[tt][0]=v.x; mk[tt][1]=v.y; mk[tt][2]=v.z; mk[tt][3]=v.w;
            }
        }

        unsigned long long a[2*NPT];
        #pragma unroll
        for (int i=0; i<2*NPT; i++) a[i] = 0ULL;

        #pragma unroll
        for (int w=0; w<WRD; w++) {
            if constexpr (OG == 16) {
                Chan2x16Loop<0, 32>::run(mk[0][w], mk[1][w], sbase + w*2048,
                                         reinterpret_cast<unsigned long long(&)[16]>(a));
            } else {
                Chan2x8Loop<0, 32>::run(mk[0][w], mk[1][w], sbase + w*1024,
                                        reinterpret_cast<unsigned long long(&)[8]>(a));
            }
        }

        // LIF for the 2 timesteps, sequentially
        #pragma unroll
        for (int tt=0; tt<2; tt++) {
            int t = chnk*2 + tt;
            uint32_t sb = 0;
            #pragma unroll
            for (int c=0; c<OG; c++) {
                float curc = (c & 1) ? hi32(a[tt*NPT + (c>>1)]) : lo32(a[tt*NPT + (c>>1)]);
                float cf = curc + bb[c];
                float mo = m[c];
                float mn = fmaf(0.95f, mo, cf) - ((mo>1.0f)?1.0f:0.0f);
                m[c] = mn;
                sb |= ((mn>1.0f)?1u:0u) << c;
            }
            sb |= __shfl_xor_sync(0xffffffffu, sb, 1);
            sb |= __shfl_xor_sync(0xffffffffu, sb, 2);

            if constexpr (COUNT) {
                #pragma unroll
                for (int c=0; c<OG; c++) cnt[c] += (float)((sb>>c)&1u);
            } else {
                size_t base = (((size_t)(t*NB+b)*HP + hp)*WP + wp)*NBY;
                if (pos == 0) {
                    if constexpr (OG == 16) {
                        *(uint16_t*)&outb[base + 2*blockIdx.y] = (uint16_t)sb;
                    } else {
                        outb[base + blockIdx.y] = (uint8_t)sb;
                    }
                }
            }
        }
    }

    if constexpr (COUNT) {
        if (pos == 0) {
            #pragma unroll
            for (int c=0; c<OG; c++)
                g_S[((size_t)(ob+c)*(HP*WP) + hp*WP + wp)*NB + b] = cnt[c];
        }
    }
}

__global__ void __launch_bounds__(128) k_l2(const float* __restrict__ wg, const float* __restrict__ bg){
    conv_body<32,64,16,128,160,128,false>(g_spk1, (uint8_t*)g_spk2, wg, bg);
}
__global__ void __launch_bounds__(128) k_l3(const float* __restrict__ wg, const float* __restrict__ bg){
    conv_body<64,64,16,64,80,128,false>(g_spk2, (uint8_t*)g_spk3, wg, bg);
}
__global__ void __launch_bounds__(128) k_l4(const float* __restrict__ wg, const float* __restrict__ bg){
    conv_body<64,128,16,32,40,128,false>(g_spk3, (uint8_t*)g_spk4, wg, bg);
}
__global__ void __launch_bounds__(128) k_l5(const float* __restrict__ wg, const float* __restrict__ bg){
    conv_body<128,128,8,16,20,128,true>(g_spk4, nullptr, wg, bg);
}

// ------------- fc1: [8,10240] @ [4096,10240]^T, spike -------------
__global__ void __launch_bounds__(128) k_fc1(const float* __restrict__ w,
                                             const float* __restrict__ bias) {
    __shared__ __align__(16) float sw[16*260];
    __shared__ __align__(16) float ss[8*260];
    int tid = threadIdx.x;
    int jl  = tid >> 3, b = tid & 7;
    int j   = blockIdx.x*16 + jl;

    float a0=0.f, a1=0.f, a2=0.f, a3=0.f;

    #pragma unroll 1
    for (int kt=0; kt<40; kt++) {
        __syncthreads();
        for (int i = tid; i < 1024; i += 128) {
            int r = i >> 6, c4 = i & 63;
            float4 v = *(const float4*)&w[(size_t)(blockIdx.x*16 + r)*10240 + kt*256 + c4*4];
            *(float4*)&sw[r*260 + c4*4] = v;
        }
        for (int i = tid; i < 2048; i += 128) {
            int k = i >> 3, bi = i & 7;
            ss[bi*260 + k] = g_S[(size_t)(kt*256 + k)*8 + bi];
        }
        __syncthreads();

        #pragma unroll 4
        for (int kk=0; kk<256; kk+=4) {
            float4 wv = *(const float4*)&sw[jl*260 + kk];
            float4 sv = *(const float4*)&ss[b*260 + kk];
            a0 = fmaf(wv.x, sv.x, a0);
            a1 = fmaf(wv.y, sv.y, a1);
            a2 = fmaf(wv.z, sv.z, a2);
            a3 = fmaf(wv.w, sv.w, a3);
        }
    }
    float mem = ((a0+a1)+(a2+a3)) + bias[j];
    g_spk1f[b*4096 + j] = (mem>1.0f) ? 1.0f : 0.0f;
}

// ------------- fc2: [8,4096] @ [4,4096]^T -> out[8,4] -------------
__global__ void __launch_bounds__(1024) k_fc2(const float* __restrict__ w,
                                              const float* __restrict__ bias,
                                              float* __restrict__ out) {
    int wid  = threadIdx.x >> 5;
    int lane = threadIdx.x & 31;
    int b = wid >> 2, i = wid & 3;
    float acc = 0.0f;
    for (int j = lane*4; j < 4096; j += 128) {
        float4 s  = *(const float4*)&g_spk1f[b*4096 + j];
        float4 wv = *(const float4*)&w[(size_t)i*4096 + j];
        acc = fmaf(wv.x, s.x, acc);
        acc = fmaf(wv.y, s.y, acc);
        acc = fmaf(wv.z, s.z, acc);
        acc = fmaf(wv.w, s.w, acc);
    }
    #pragma unroll
    for (int off=16; off; off>>=1) acc += __shfl_xor_sync(0xffffffffu, acc, off);
    if (lane == 0) out[b*4 + i] = acc + bias[i];
}

extern "C" void kernel_launch(void* const* d_in, const int* in_sizes, int n_in,
                              void* d_out, int out_size) {
    const float* x     = (const float*)d_in[0];
    const float* w1    = (const float*)d_in[1];
    const float* b1    = (const float*)d_in[2];
    const float* w2    = (const float*)d_in[3];
    const float* b2    = (const float*)d_in[4];
    const float* w3    = (const float*)d_in[5];
    const float* b3    = (const float*)d_in[6];
    const float* w4    = (const float*)d_in[7];
    const float* b4    = (const float*)d_in[8];
    const float* w5    = (const float*)d_in[9];
    const float* b5    = (const float*)d_in[10];
    const float* fc1_w = (const float*)d_in[11];
    const float* fc1_b = (const float*)d_in[12];
    const float* fc2_w = (const float*)d_in[13];
    const float* fc2_b = (const float*)d_in[14];

    k_l1<<<5120, 256>>>(x, w1, b1);                   // 1.31M threads, 16ch each
    { dim3 g(1280, 4); k_l2<<<g, 128>>>(w2, b2); }    // OG=16
    { dim3 g(320, 4);  k_l3<<<g, 128>>>(w3, b3); }    // OG=16
    { dim3 g(80, 8);   k_l4<<<g, 128>>>(w4, b4); }    // OG=16
    { dim3 g(20, 16);  k_l5<<<g, 128>>>(w5, b5); }    // OG=8 + counts
    k_fc1<<<256, 128>>>(fc1_w, fc1_b);
    k_fc2<<<1, 1024>>>(fc2_w, fc2_b, (float*)d_out);
}

// round 15
// speedup vs baseline: 1.1155x; 1.0002x over previous
#include <cuda_runtime.h>
#include <cstdint>
#include <cstddef>

#define T_STEPS 10
#define NB 8

// ---------------- scratch (device globals; no allocation) ----------------
__device__ uint32_t g_spk1[T_STEPS*NB*128*160];      // 32ch masks
__device__ uint32_t g_spk2[T_STEPS*NB*64*80*2];      // 64ch masks
__device__ uint32_t g_spk3[T_STEPS*NB*32*40*2];      // 64ch masks
__device__ uint32_t g_spk4[T_STEPS*NB*16*20*4];      // 128ch masks
__device__ float    g_S[10240*NB];                   // spike counts [k][b]
__device__ float    g_spk1f[NB*4096];                // fc1 spikes

__device__ __forceinline__ float lo32(unsigned long long v){ return __uint_as_float((uint32_t)v); }
__device__ __forceinline__ float hi32(unsigned long long v){ return __uint_as_float((uint32_t)(v>>32)); }

// ---------------- layer 1: conv 2->32 @256x320 + LIF + pool ----------------
__global__ void __launch_bounds__(256) k_l1(const float* __restrict__ x,
                                            const float* __restrict__ w1,
                                            const float* __restrict__ b1) {
    int id  = blockIdx.x*256 + threadIdx.x;
    int pos = id & 3, dh = pos >> 1, dw = pos & 1;
    int g   = (id >> 2) & 1;
    int rid = id >> 3;
    int wp  = rid % 160; rid /= 160;
    int hp  = rid % 128;
    int b   = rid / 128;

    float w0[16], w1r[16], bb[16], m[16];
    #pragma unroll
    for (int oo=0; oo<16; oo++) {
        int o = g*16+oo;
        w0[oo] = w1[2*o]; w1r[oo] = w1[2*o+1]; bb[oo] = b1[o];
        m[oo]  = 0.0f;
    }

    const float* xb0 = x + ((size_t)b)*163840 + (2*hp+dh)*320 + (2*wp+dw);
    #pragma unroll 1
    for (int t=0; t<T_STEPS; t++) {
        const float* xb = xb0 + (size_t)t*NB*163840;
        float x0 = xb[0];
        float x1 = xb[81920];
        uint32_t sb = 0;
        #pragma unroll
        for (int oo=0; oo<16; oo++) {
            float cur = fmaf(w1r[oo], x1, w0[oo]*x0) + bb[oo];
            float mo  = m[oo];
            float mn  = fmaf(0.95f, mo, cur) - ((mo>1.0f)?1.0f:0.0f);
            m[oo] = mn;
            sb |= ((mn>1.0f)?1u:0u) << oo;
        }
        sb <<= (g*16);
        sb |= __shfl_xor_sync(0xffffffffu, sb, 1);
        sb |= __shfl_xor_sync(0xffffffffu, sb, 2);
        sb |= __shfl_xor_sync(0xffffffffu, sb, 4);
        if ((id & 7) == 0)
            g_spk1[((size_t)(t*NB+b)*128 + hp)*160 + wp] = sb;
    }
}

// ---- OG=16, 2 timesteps per step: 4 LDS.128 + 6 ALU amortized over 16 FFMA2 ----
// Bit-exact per (t, output ch): one rn-add per set bit, ascending channel order.
template<int C>
__device__ __forceinline__ void chan2x16(uint32_t k0, uint32_t k1,
                                         uint32_t sbw, unsigned long long (&a)[16]) {
    asm volatile("{\n\t"
        ".reg .b32 b0,b1;\n\t"
        ".reg .b64 s0,s1,w0,w1,w2,w3,w4,w5,w6,w7;\n\t"
        "bfe.s32 b0, %16, %18, 1;\n\t"
        "bfe.s32 b1, %17, %18, 1;\n\t"
        "and.b32 b0, b0, 0x3f800000;\n\t"
        "and.b32 b1, b1, 0x3f800000;\n\t"
        "mov.b64 s0, {b0, b0};\n\t"
        "mov.b64 s1, {b1, b1};\n\t"
        "ld.shared.v2.u64 {w0,w1}, [%19+%20];\n\t"
        "ld.shared.v2.u64 {w2,w3}, [%19+%21];\n\t"
        "ld.shared.v2.u64 {w4,w5}, [%19+%22];\n\t"
        "ld.shared.v2.u64 {w6,w7}, [%19+%23];\n\t"
        "fma.rn.f32x2 %0, w0, s0, %0;\n\t"
        "fma.rn.f32x2 %1, w1, s0, %1;\n\t"
        "fma.rn.f32x2 %2, w2, s0, %2;\n\t"
        "fma.rn.f32x2 %3, w3, s0, %3;\n\t"
        "fma.rn.f32x2 %4, w4, s0, %4;\n\t"
        "fma.rn.f32x2 %5, w5, s0, %5;\n\t"
        "fma.rn.f32x2 %6, w6, s0, %6;\n\t"
        "fma.rn.f32x2 %7, w7, s0, %7;\n\t"
        "fma.rn.f32x2 %8, w0, s1, %8;\n\t"
        "fma.rn.f32x2 %9, w1, s1, %9;\n\t"
        "fma.rn.f32x2 %10, w2, s1, %10;\n\t"
        "fma.rn.f32x2 %11, w3, s1, %11;\n\t"
        "fma.rn.f32x2 %12, w4, s1, %12;\n\t"
        "fma.rn.f32x2 %13, w5, s1, %13;\n\t"
        "fma.rn.f32x2 %14, w6, s1, %14;\n\t"
        "fma.rn.f32x2 %15, w7, s1, %15;\n\t}"
        : "+l"(a[0]),  "+l"(a[1]),  "+l"(a[2]),  "+l"(a[3]),
          "+l"(a[4]),  "+l"(a[5]),  "+l"(a[6]),  "+l"(a[7]),
          "+l"(a[8]),  "+l"(a[9]),  "+l"(a[10]), "+l"(a[11]),
          "+l"(a[12]), "+l"(a[13]), "+l"(a[14]), "+l"(a[15])
        : "r"(k0), "r"(k1), "n"(C), "r"(sbw),
          "n"(C*64), "n"(C*64+16), "n"(C*64+32), "n"(C*64+48));
}

template<int C, int N>
struct Chan2x16Loop {
    static __device__ __forceinline__ void run(uint32_t k0, uint32_t k1,
                                               uint32_t sbw, unsigned long long (&a)[16]) {
        chan2x16<C>(k0, k1, sbw, a);
        Chan2x16Loop<C+1, N>::run(k0, k1, sbw, a);
    }
};
template<int N>
struct Chan2x16Loop<N, N> {
    static __device__ __forceinline__ void run(uint32_t, uint32_t,
                                               uint32_t, unsigned long long (&)[16]) {}
};

// ---- OG=8 variant (for l5/COUNT) ----
template<int C>
__device__ __forceinline__ void chan2x8(uint32_t k0, uint32_t k1,
                                        uint32_t sbw, unsigned long long (&a)[8]) {
    asm volatile("{\n\t"
        ".reg .b32 b0,b1;\n\t"
        ".reg .b64 s0,s1,w0,w1,w2,w3;\n\t"
        "bfe.s32 b0, %8, %10, 1;\n\t"
        "bfe.s32 b1, %9, %10, 1;\n\t"
        "and.b32 b0, b0, 0x3f800000;\n\t"
        "and.b32 b1, b1, 0x3f800000;\n\t"
        "mov.b64 s0, {b0, b0};\n\t"
        "mov.b64 s1, {b1, b1};\n\t"
        "ld.shared.v2.u64 {w0,w1}, [%11+%12];\n\t"
        "ld.shared.v2.u64 {w2,w3}, [%11+%13];\n\t"
        "fma.rn.f32x2 %0, w0, s0, %0;\n\t"
        "fma.rn.f32x2 %1, w1, s0, %1;\n\t"
        "fma.rn.f32x2 %2, w2, s0, %2;\n\t"
        "fma.rn.f32x2 %3, w3, s0, %3;\n\t"
        "fma.rn.f32x2 %4, w0, s1, %4;\n\t"
        "fma.rn.f32x2 %5, w1, s1, %5;\n\t"
        "fma.rn.f32x2 %6, w2, s1, %6;\n\t"
        "fma.rn.f32x2 %7, w3, s1, %7;\n\t}"
        : "+l"(a[0]), "+l"(a[1]), "+l"(a[2]), "+l"(a[3]),
          "+l"(a[4]), "+l"(a[5]), "+l"(a[6]), "+l"(a[7])
        : "r"(k0), "r"(k1),
          "n"(C), "r"(sbw), "n"(C*32), "n"(C*32+16));
}

template<int C, int N>
struct Chan2x8Loop {
    static __device__ __forceinline__ void run(uint32_t k0, uint32_t k1,
                                               uint32_t sbw, unsigned long long (&a)[8]) {
        chan2x8<C>(k0, k1, sbw, a);
        Chan2x8Loop<C+1, N>::run(k0, k1, sbw, a);
    }
};
template<int N>
struct Chan2x8Loop<N, N> {
    static __device__ __forceinline__ void run(uint32_t, uint32_t,
                                               uint32_t, unsigned long long (&)[8]) {}
};

// ------------- conv(1x1 over bitmask spikes)+LIF+pool, T in 5 chunks of 2 -------------
// Spill-safe shape: #pragma unroll 1 chunk loop, loop-local arrays only.
// Bias lives in SHARED (sbb) to save 16 regs per thread.
template<int CIN, int COUT, int OG, int HIN, int WIN, int BS, bool COUNT>
__device__ __forceinline__ void conv_body(const uint32_t* __restrict__ in,
                                          uint8_t* __restrict__ outb,
                                          const float* __restrict__ wg,
                                          const float* __restrict__ bg) {
    constexpr int WRD = CIN/32;
    constexpr int HP  = HIN/2, WP = WIN/2;
    constexpr int NBY = COUT/8;
    constexpr int NPT = OG/2;   // acc pairs per timestep

    __shared__ __align__(16) float wt[CIN*OG];      // wt[c][o] (transposed)
    __shared__ float sbb[OG];
    const int ob = blockIdx.y * OG;
    for (int idx = threadIdx.x; idx < CIN*OG; idx += BS) {
        int c = idx / OG, o = idx % OG;
        wt[c*OG + o] = wg[(size_t)(ob+o)*CIN + c];
    }
    if (threadIdx.x < OG) sbb[threadIdx.x] = bg[ob + threadIdx.x];
    __syncthreads();

    uint32_t sbase;
    asm("{ .reg .u64 t0; cvta.to.shared.u64 t0, %1; cvt.u32.u64 %0, t0; }"
        : "=r"(sbase) : "l"(wt));

    int id  = blockIdx.x*BS + threadIdx.x;
    int pos = id & 3, dh = pos >> 1, dw = pos & 1;
    int rid = id >> 2;
    int wp  = rid % WP; rid /= WP;
    int hp  = rid % HP;
    int b   = rid / HP;

    float m[OG], cnt[OG];
    #pragma unroll
    for (int c=0; c<OG; c++) { m[c] = 0.0f; cnt[c] = 0.0f; }

    const uint32_t* ibase = in + (((size_t)b*HIN + 2*hp+dh)*WIN + (2*wp+dw))*WRD;
    const size_t tstride  = (size_t)NB*HIN*WIN*WRD;

    #pragma unroll 1
    for (int chnk=0; chnk<5; chnk++) {
        // stage 2 timesteps of input masks
        uint32_t mk[2][WRD];
        #pragma unroll
        for (int tt=0; tt<2; tt++) {
            const uint32_t* ip = ibase + (size_t)(chnk*2+tt)*tstride;
            if constexpr (WRD == 1) {
                mk[tt][0] = ip[0];
            } else if constexpr (WRD == 2) {
                uint2 v = *(const uint2*)ip; mk[tt][0]=v.x; mk[tt][1]=v.y;
            } else {
                uint4 v = *(const uint4*)ip;
                mk[tt][0]=v.x; mk[tt][1]=v.y; mk[tt][2]=v.z; mk[tt][3]=v.w;
            }
        }

        unsigned long long a[2*NPT];
        #pragma unroll
        for (int i=0; i<2*NPT; i++) a[i] = 0ULL;

        #pragma unroll
        for (int w=0; w<WRD; w++) {
            if constexpr (OG == 16) {
                Chan2x16Loop<0, 32>::run(mk[0][w], mk[1][w], sbase + w*2048,
                                         reinterpret_cast<unsigned long long(&)[16]>(a));
            } else {
                Chan2x8Loop<0, 32>::run(mk[0][w], mk[1][w], sbase + w*1024,
                                        reinterpret_cast<unsigned long long(&)[8]>(a));
            }
        }

        // LIF for the 2 timesteps, sequentially
        #pragma unroll
        for (int tt=0; tt<2; tt++) {
            int t = chnk*2 + tt;
            uint32_t sb = 0;
            #pragma unroll
            for (int c=0; c<OG; c++) {
                float curc = (c & 1) ? hi32(a[tt*NPT + (c>>1)]) : lo32(a[tt*NPT + (c>>1)]);
                float cf = curc + sbb[c];
                float mo = m[c];
                float mn = fmaf(0.95f, mo, cf) - ((mo>1.0f)?1.0f:0.0f);
                m[c] = mn;
                sb |= ((mn>1.0f)?1u:0u) << c;
            }
            sb |= __shfl_xor_sync(0xffffffffu, sb, 1);
            sb |= __shfl_xor_sync(0xffffffffu, sb, 2);

            if constexpr (COUNT) {
                #pragma unroll
                for (int c=0; c<OG; c++) cnt[c] += (float)((sb>>c)&1u);
            } else {
                size_t base = (((size_t)(t*NB+b)*HP + hp)*WP + wp)*NBY;
                if (pos == 0) {
                    if constexpr (OG == 16) {
                        *(uint16_t*)&outb[base + 2*blockIdx.y] = (uint16_t)sb;
                    } else {
                        outb[base + blockIdx.y] = (uint8_t)sb;
                    }
                }
            }
        }
    }

    if constexpr (COUNT) {
        if (pos == 0) {
            #pragma unroll
            for (int c=0; c<OG; c++)
                g_S[((size_t)(ob+c)*(HP*WP) + hp*WP + wp)*NB + b] = cnt[c];
        }
    }
}

__global__ void __launch_bounds__(128) k_l2(const float* __restrict__ wg, const float* __restrict__ bg){
    conv_body<32,64,16,128,160,128,false>(g_spk1, (uint8_t*)g_spk2, wg, bg);
}
__global__ void __launch_bounds__(128) k_l3(const float* __restrict__ wg, const float* __restrict__ bg){
    conv_body<64,64,16,64,80,128,false>(g_spk2, (uint8_t*)g_spk3, wg, bg);
}
__global__ void __launch_bounds__(64) k_l4(const float* __restrict__ wg, const float* __restrict__ bg){
    conv_body<64,128,16,32,40,64,false>(g_spk3, (uint8_t*)g_spk4, wg, bg);
}
__global__ void __launch_bounds__(64) k_l5(const float* __restrict__ wg, const float* __restrict__ bg){
    conv_body<128,128,8,16,20,64,true>(g_spk4, nullptr, wg, bg);
}

// ------------- fc1: [8,10240] @ [4096,10240]^T, spike -------------
__global__ void __launch_bounds__(128) k_fc1(const float* __restrict__ w,
                                             const float* __restrict__ bias) {
    __shared__ __align__(16) float sw[16*260];
    __shared__ __align__(16) float ss[8*260];
    int tid = threadIdx.x;
    int jl  = tid >> 3, b = tid & 7;
    int j   = blockIdx.x*16 + jl;

    float a0=0.f, a1=0.f, a2=0.f, a3=0.f;

    #pragma unroll 1
    for (int kt=0; kt<40; kt++) {
        __syncthreads();
        for (int i = tid; i < 1024; i += 128) {
            int r = i >> 6, c4 = i & 63;
            float4 v = *(const float4*)&w[(size_t)(blockIdx.x*16 + r)*10240 + kt*256 + c4*4];
            *(float4*)&sw[r*260 + c4*4] = v;
        }
        for (int i = tid; i < 2048; i += 128) {
            int k = i >> 3, bi = i & 7;
            ss[bi*260 + k] = g_S[(size_t)(kt*256 + k)*8 + bi];
        }
        __syncthreads();

        #pragma unroll 4
        for (int kk=0; kk<256; kk+=4) {
            float4 wv = *(const float4*)&sw[jl*260 + kk];
            float4 sv = *(const float4*)&ss[b*260 + kk];
            a0 = fmaf(wv.x, sv.x, a0);
            a1 = fmaf(wv.y, sv.y, a1);
            a2 = fmaf(wv.z, sv.z, a2);
            a3 = fmaf(wv.w, sv.w, a3);
        }
    }
    float mem = ((a0+a1)+(a2+a3)) + bias[j];
    g_spk1f[b*4096 + j] = (mem>1.0f) ? 1.0f : 0.0f;
}

// ------------- fc2: [8,4096] @ [4,4096]^T -> out[8,4] -------------
__global__ void __launch_bounds__(1024) k_fc2(const float* __restrict__ w,
                                              const float* __restrict__ bias,
                                              float* __restrict__ out) {
    int wid  = threadIdx.x >> 5;
    int lane = threadIdx.x & 31;
    int b = wid >> 2, i = wid & 3;
    float acc = 0.0f;
    for (int j = lane*4; j < 4096; j += 128) {
        float4 s  = *(const float4*)&g_spk1f[b*4096 + j];
        float4 wv = *(const float4*)&w[(size_t)i*4096 + j];
        acc = fmaf(wv.x, s.x, acc);
        acc = fmaf(wv.y, s.y, acc);
        acc = fmaf(wv.z, s.z, acc);
        acc = fmaf(wv.w, s.w, acc);
    }
    #pragma unroll
    for (int off=16; off; off>>=1) acc += __shfl_xor_sync(0xffffffffu, acc, off);
    if (lane == 0) out[b*4 + i] = acc + bias[i];
}

extern "C" void kernel_launch(void* const* d_in, const int* in_sizes, int n_in,
                              void* d_out, int out_size) {
    const float* x     = (const float*)d_in[0];
    const float* w1    = (const float*)d_in[1];
    const float* b1    = (const float*)d_in[2];
    const float* w2    = (const float*)d_in[3];
    const float* b2    = (const float*)d_in[4];
    const float* w3    = (const float*)d_in[5];
    const float* b3    = (const float*)d_in[6];
    const float* w4    = (const float*)d_in[7];
    const float* b4    = (const float*)d_in[8];
    const float* w5    = (const float*)d_in[9];
    const float* b5    = (const float*)d_in[10];
    const float* fc1_w = (const float*)d_in[11];
    const float* fc1_b = (const float*)d_in[12];
    const float* fc2_w = (const float*)d_in[13];
    const float* fc2_b = (const float*)d_in[14];

    k_l1<<<5120, 256>>>(x, w1, b1);                   // 1.31M threads, 16ch each
    { dim3 g(1280, 4); k_l2<<<g, 128>>>(w2, b2); }    // OG=16
    { dim3 g(320, 4);  k_l3<<<g, 128>>>(w3, b3); }    // OG=16
    { dim3 g(160, 8);  k_l4<<<g, 64>>>(w4, b4); }     // OG=16, BS=64 -> 1280 CTAs
    { dim3 g(40, 16);  k_l5<<<g, 64>>>(w5, b5); }     // OG=8 + counts, BS=64 -> 640 CTAs
    k_fc1<<<256, 128>>>(fc1_w, fc1_b);
    k_fc2<<<1, 1024>>>(fc2_w, fc2_b, (float*)d_out);
}